// round 2
// baseline (speedup 1.0000x reference)
#include <cuda_runtime.h>

// IndRNN recurrence: h_t = relu(h_{t-1} * w[h] + x[t,b,h]), out[t,b,h] = h_t
// x: [T, B, H] fp32, w: [H], h0: [B, H] (zeros), out: [T, B, H]
// One thread per (b,h) channel; sequential scan over T.
// R2: software-pipelined double buffering — loads for the NEXT chunk are
// issued before computing the current chunk, so every warp keeps a full
// chunk (16 lines / 4 KB) in flight across the compute/store tail.

#define T_STEPS 1024
#define B_DIM 64
#define H_DIM 1024
#define BH (B_DIM * H_DIM)
#define UNROLL 16

__global__ __launch_bounds__(128, 16)
void indrnn_kernel(const float* __restrict__ x,
                   const float* __restrict__ w,
                   const float* __restrict__ h0,
                   float* __restrict__ out) {
    const int idx = blockIdx.x * blockDim.x + threadIdx.x;  // 0 .. BH-1
    const int hcol = idx & (H_DIM - 1);

    const float wv = __ldg(&w[hcol]);
    float h = h0[idx];

    const float* xp = x + idx;
    float* op = out + idx;

    float bufA[UNROLL], bufB[UNROLL];

    // Prologue: load chunk 0 into A
    #pragma unroll
    for (int i = 0; i < UNROLL; i++)
        bufA[i] = __ldg(xp + (long long)i * BH);

    // Steady state: process 2 chunks per iteration (A then B), always
    // prefetching one chunk ahead of the compute.
    #pragma unroll 1
    for (int t = 0; t < T_STEPS - 2 * UNROLL; t += 2 * UNROLL) {
        // Prefetch chunk t+U into B
        #pragma unroll
        for (int i = 0; i < UNROLL; i++)
            bufB[i] = __ldg(xp + (long long)(t + UNROLL + i) * BH);
        // Compute + store chunk t from A
        #pragma unroll
        for (int i = 0; i < UNROLL; i++) {
            h = fmaxf(fmaf(h, wv, bufA[i]), 0.0f);
            op[(long long)(t + i) * BH] = h;
        }
        // Prefetch chunk t+2U into A
        #pragma unroll
        for (int i = 0; i < UNROLL; i++)
            bufA[i] = __ldg(xp + (long long)(t + 2 * UNROLL + i) * BH);
        // Compute + store chunk t+U from B
        #pragma unroll
        for (int i = 0; i < UNROLL; i++) {
            h = fmaxf(fmaf(h, wv, bufB[i]), 0.0f);
            op[(long long)(t + UNROLL + i) * BH] = h;
        }
    }

    // Epilogue: last two chunks (A already loaded; load B, compute both)
    {
        const int t = T_STEPS - 2 * UNROLL;
        #pragma unroll
        for (int i = 0; i < UNROLL; i++)
            bufB[i] = __ldg(xp + (long long)(t + UNROLL + i) * BH);
        #pragma unroll
        for (int i = 0; i < UNROLL; i++) {
            h = fmaxf(fmaf(h, wv, bufA[i]), 0.0f);
            op[(long long)(t + i) * BH] = h;
        }
        #pragma unroll
        for (int i = 0; i < UNROLL; i++) {
            h = fmaxf(fmaf(h, wv, bufB[i]), 0.0f);
            op[(long long)(t + UNROLL + i) * BH] = h;
        }
    }
}

extern "C" void kernel_launch(void* const* d_in, const int* in_sizes, int n_in,
                              void* d_out, int out_size) {
    const float* x  = (const float*)d_in[0];   // [T, B, H]
    const float* w  = (const float*)d_in[1];   // [H]
    const float* h0 = (const float*)d_in[2];   // [B, H]
    float* out = (float*)d_out;                // [T, B, H]

    const int threads = 128;
    const int blocks = BH / threads;           // 512 blocks
    indrnn_kernel<<<blocks, threads>>>(x, w, h0, out);
}

// round 4
// speedup vs baseline: 1.0213x; 1.0213x over previous
#include <cuda_runtime.h>

// IndRNN recurrence: h_t = relu(h_{t-1} * w[h] + x[t,b,h]), out[t,b,h] = h_t
// x: [T, B, H] fp32, w: [H], h0: [B, H], out: [T, B, H]. T=1024, B=64, H=1024.
// One thread per (b,h) channel, sequential over T.
// R3: rotating 16-slot prefetch ring with NO occupancy-forcing launch bounds.
// (R2 failed because __launch_bounds__(128,16) capped regs at 32, making a
// 16-deep prefetch buffer impossible — ptxas serialized the loads.)

#define T_STEPS 1024
#define B_DIM 64
#define H_DIM 1024
#define BH (B_DIM * H_DIM)
#define PF 16

__global__ __launch_bounds__(128)
void indrnn_kernel(const float* __restrict__ x,
                   const float* __restrict__ w,
                   const float* __restrict__ h0,
                   float* __restrict__ out) {
    const int idx = blockIdx.x * blockDim.x + threadIdx.x;  // 0 .. BH-1
    const int hcol = idx & (H_DIM - 1);

    const float wv = __ldg(&w[hcol]);
    float h = h0[idx];

    const float* xp = x + idx;        // points at x[t_base + 0]
    float* op = out + idx;

    float buf[PF];

    // Prologue: fill the ring with steps 0..PF-1
    #pragma unroll
    for (int i = 0; i < PF; i++)
        buf[i] = __ldg(xp + i * BH);

    const float* xpre = xp + PF * BH; // points at x[t_base + PF]

    // Steady state: consume slot i, immediately refill it with step t+PF+i.
    // The refill load is independent of the recurrence chain, so ~16 LDGs
    // stay continuously in flight per warp.
    #pragma unroll 1
    for (int t = 0; t < T_STEPS - PF; t += PF) {
        #pragma unroll
        for (int i = 0; i < PF; i++) {
            const float xv = buf[i];
            buf[i] = __ldg(xpre + i * BH);       // prefetch t+PF+i
            h = fmaxf(fmaf(h, wv, xv), 0.0f);
            op[i * BH] = h;
        }
        xpre += PF * BH;
        op   += PF * BH;
    }

    // Epilogue: last PF steps, ring already full
    #pragma unroll
    for (int i = 0; i < PF; i++) {
        h = fmaxf(fmaf(h, wv, buf[i]), 0.0f);
        op[i * BH] = h;
    }
}

extern "C" void kernel_launch(void* const* d_in, const int* in_sizes, int n_in,
                              void* d_out, int out_size) {
    const float* x  = (const float*)d_in[0];   // [T, B, H]
    const float* w  = (const float*)d_in[1];   // [H]
    const float* h0 = (const float*)d_in[2];   // [B, H]
    float* out = (float*)d_out;                // [T, B, H]

    const int threads = 128;
    const int blocks = BH / threads;           // 512 blocks
    indrnn_kernel<<<blocks, threads>>>(x, w, h0, out);
}

// round 5
// speedup vs baseline: 1.0220x; 1.0006x over previous
#include <cuda_runtime.h>

// IndRNN recurrence: h_t = relu(h_{t-1} * w[h] + x[t,b,h]), out[t,b,h] = h_t
// x: [T, B, H] fp32, w: [H], h0: [B, H], out: [T, B, H]. T=1024, B=64, H=1024.
// One thread per (b,h) channel, sequential over T. PF=16 rotating prefetch ring.
// R4: 64-thread blocks -> 1024 CTAs over 148 SMs (6.92/SM, imbalance 1.01)
// instead of 512 CTAs (3.46/SM, imbalance 1.16). R2/R3 showed per-warp MLP
// restructuring is flat at ~67% DRAM; the gap is wave imbalance, not latency.

#define T_STEPS 1024
#define B_DIM 64
#define H_DIM 1024
#define BH (B_DIM * H_DIM)
#define PF 16

__global__ __launch_bounds__(64)
void indrnn_kernel(const float* __restrict__ x,
                   const float* __restrict__ w,
                   const float* __restrict__ h0,
                   float* __restrict__ out) {
    const int idx = blockIdx.x * blockDim.x + threadIdx.x;  // 0 .. BH-1
    const int hcol = idx & (H_DIM - 1);

    const float wv = __ldg(&w[hcol]);
    float h = h0[idx];

    const float* xp = x + idx;
    float* op = out + idx;

    float buf[PF];

    // Prologue: fill the ring with steps 0..PF-1
    #pragma unroll
    for (int i = 0; i < PF; i++)
        buf[i] = __ldg(xp + i * BH);

    const float* xpre = xp + PF * BH;

    // Steady state: consume slot i, immediately refill it with step t+PF+i.
    #pragma unroll 1
    for (int t = 0; t < T_STEPS - PF; t += PF) {
        #pragma unroll
        for (int i = 0; i < PF; i++) {
            const float xv = buf[i];
            buf[i] = __ldg(xpre + i * BH);       // prefetch t+PF+i
            h = fmaxf(fmaf(h, wv, xv), 0.0f);
            op[i * BH] = h;
        }
        xpre += PF * BH;
        op   += PF * BH;
    }

    // Epilogue: last PF steps, ring already full
    #pragma unroll
    for (int i = 0; i < PF; i++) {
        h = fmaxf(fmaf(h, wv, buf[i]), 0.0f);
        op[i * BH] = h;
    }
}

extern "C" void kernel_launch(void* const* d_in, const int* in_sizes, int n_in,
                              void* d_out, int out_size) {
    const float* x  = (const float*)d_in[0];   // [T, B, H]
    const float* w  = (const float*)d_in[1];   // [H]
    const float* h0 = (const float*)d_in[2];   // [B, H]
    float* out = (float*)d_out;                // [T, B, H]

    const int threads = 64;
    const int blocks = BH / threads;           // 1024 blocks -> 6.92 CTAs/SM
    indrnn_kernel<<<blocks, threads>>>(x, w, h0, out);
}

// round 6
// speedup vs baseline: 1.1934x; 1.1677x over previous
#include <cuda_runtime.h>

// IndRNN recurrence: h_t = relu(h_{t-1} * w[h] + x[t,b,h]), out[t,b,h] = h_t
// x: [T, B, H] fp32, w: [H], h0: [B, H], out: [T, B, H]. T=1024, B=64, H=1024.
// R5: float2 per thread (32768 threads), PF=32 prefetch ring (8 MB in flight
// chip-wide), and streaming cache hints (__ldcs / __stcs) — read-once /
// write-once data marked evict-first so L2 isn't churned by write-allocate.
// R1-R4 established ~5.8 TB/s effective regardless of MLP structure or CTA
// granularity -> the lever is memory-system scheduling efficiency.

#define T_STEPS 1024
#define B_DIM 64
#define H_DIM 1024
#define BH (B_DIM * H_DIM)
#define BH2 (BH / 2)      // float2 elements per time step
#define H2 (H_DIM / 2)
#define PF 32

__global__ __launch_bounds__(64)
void indrnn_kernel(const float2* __restrict__ x,
                   const float2* __restrict__ w,
                   const float2* __restrict__ h0,
                   float2* __restrict__ out) {
    const int idx = blockIdx.x * blockDim.x + threadIdx.x;  // 0 .. BH2-1
    const int hcol = idx & (H2 - 1);

    const float2 wv = w[hcol];
    float2 h = h0[idx];

    const float2* xp = x + idx;
    float2* op = out + idx;

    float2 buf[PF];

    // Prologue: fill the ring with steps 0..PF-1
    #pragma unroll
    for (int i = 0; i < PF; i++)
        buf[i] = __ldcs(xp + i * BH2);

    const float2* xpre = xp + PF * BH2;

    // Steady state: consume slot i, immediately refill with step t+PF+i.
    #pragma unroll 1
    for (int t = 0; t < T_STEPS - PF; t += PF) {
        #pragma unroll
        for (int i = 0; i < PF; i++) {
            const float2 xv = buf[i];
            buf[i] = __ldcs(xpre + i * BH2);     // prefetch t+PF+i
            h.x = fmaxf(fmaf(h.x, wv.x, xv.x), 0.0f);
            h.y = fmaxf(fmaf(h.y, wv.y, xv.y), 0.0f);
            __stcs(op + i * BH2, h);
        }
        xpre += PF * BH2;
        op   += PF * BH2;
    }

    // Epilogue: last PF steps, ring already full
    #pragma unroll
    for (int i = 0; i < PF; i++) {
        const float2 xv = buf[i];
        h.x = fmaxf(fmaf(h.x, wv.x, xv.x), 0.0f);
        h.y = fmaxf(fmaf(h.y, wv.y, xv.y), 0.0f);
        __stcs(op + i * BH2, h);
    }
}

extern "C" void kernel_launch(void* const* d_in, const int* in_sizes, int n_in,
                              void* d_out, int out_size) {
    const float2* x  = (const float2*)d_in[0];   // [T, B, H]
    const float2* w  = (const float2*)d_in[1];   // [H]
    const float2* h0 = (const float2*)d_in[2];   // [B, H]
    float2* out = (float2*)d_out;                // [T, B, H]

    const int threads = 64;
    const int blocks = BH2 / threads;            // 512 blocks
    indrnn_kernel<<<blocks, threads>>>(x, w, h0, out);
}